// round 2
// baseline (speedup 1.0000x reference)
#include <cuda_runtime.h>
#include <cstdint>

// Problem constants (fixed by the dataset):
//   adj: (B=2, N=2048, N=2048, F=16) fp32
//   filter_size f=8, stride=4  -> starts = 0..2040 step 4 -> S=511
//   off-diagonal offsets: local in [0,64) with local % 9 != 0 -> 56 offsets
//   out: (B, S, 56*F) fp32 = (2, 511, 896) = 915712 floats
//
// off -> local mapping (skip every 9th starting at 0): local = off + 1 + off/8
//   ii = local / 8, jj = local % 8
//   row = s*stride + ii, col = s*stride + jj
//   src element base = (((b*N + row)*N + col) * F)
//
// One thread per float4: 16 features = 4 quads. Output layout is
// out[b][s][off*F + f] -> float4 index = ((b*S + s)*56 + off)*4 + quad,
// which is exactly the linear thread id -> fully coalesced stores.

namespace {
constexpr int B = 2;
constexpr int N = 2048;
constexpr int F = 16;
constexpr int FS = 8;        // filter_size
constexpr int STRIDE = 4;
constexpr int S = (N - FS) / STRIDE + 1;   // 511
constexpr int NOFF = FS * FS - FS;          // 56
constexpr int QUADS = F / 4;                // 4
constexpr long long TOTAL_F4 = (long long)B * S * NOFF * QUADS;  // 228928
}

__global__ void sparse_diag_unfold_kernel(const float4* __restrict__ adj,
                                          float4* __restrict__ out) {
    int tid = blockIdx.x * blockDim.x + threadIdx.x;
    if (tid >= (int)TOTAL_F4) return;

    int quad = tid & 3;                 // QUADS = 4
    int rest = tid >> 2;                // (b*S + s)*56 + off
    int off  = rest % NOFF;
    int bs   = rest / NOFF;             // b*S + s
    int s    = bs % S;
    int b    = bs / S;

    int local = off + 1 + (off >> 3);   // skip diagonal entries
    int ii = local >> 3;
    int jj = local & 7;

    int row = s * STRIDE + ii;
    int col = s * STRIDE + jj;

    // float4 index into adj: (((b*N + row)*N + col) * F + quad*4) / 4
    long long src = ((((long long)b * N + row) * N + col) * (F / 4)) + quad;

    out[tid] = adj[src];
}

extern "C" void kernel_launch(void* const* d_in, const int* in_sizes, int n_in,
                              void* d_out, int out_size) {
    const float4* adj = (const float4*)d_in[0];
    float4* out = (float4*)d_out;

    const int threads = 256;
    const int total = (int)TOTAL_F4;
    const int blocks = (total + threads - 1) / threads;
    sparse_diag_unfold_kernel<<<blocks, threads>>>(adj, out);
}